// round 11
// baseline (speedup 1.0000x reference)
#include <cuda_runtime.h>
#include <math.h>

#define NQ 300
#define NF 8
#define BS 2
#define HW 96
#define HWHW 9216
#define D_TOT 73728.0f   // NF*H*W
#define L2E 1.4426950408889634f
#define LN2 0.6931471805599453f

// Scratch (static __device__ — no allocation)
__device__ float g_focal [BS*NF*NQ];
__device__ float g_ssum  [BS*NF*NQ];
__device__ float g_stsum [BS*NF*NQ];
__device__ float g_colmax[BS*NF*NQ*HW];  // src_y pieces: max over h
__device__ float g_rowmax[BS*NF*NQ*HW];  // src_x pieces: max over w
__device__ float g_tcolmax[BS*NF*HW];
__device__ float g_trowmax[BS*NF*HW];
__device__ float g_tsum  [BS*NF];
__device__ float g_S[BS*NF*HWHW];        // per (bf,pixel): t ? -log2e : +log2e
__device__ float g_V[BS*HWHW];           // per (b,pixel): vpad ? 0 : 1

// ---------------------------------------------------------------------------
// Fill the sign / pad multiplier arrays (one pass, tiny).
// ---------------------------------------------------------------------------
__global__ __launch_bounds__(256) void fill_sv(
    const float* __restrict__ tmask, const unsigned char* __restrict__ vpad)
{
    const int bf = blockIdx.x;
    const float* __restrict__ T = tmask + (size_t)bf * HWHW;
    for (int i = threadIdx.x; i < HWHW; i += 256)
        g_S[(size_t)bf*HWHW + i] = (T[i] != 0.f) ? -L2E : L2E;
    if (bf < BS) {
        const unsigned char* __restrict__ VP = vpad + (size_t)bf * HWHW;
        for (int i = threadIdx.x; i < HWHW; i += 256)
            g_V[(size_t)bf*HWHW + i] = VP[i] ? 0.f : 1.f;
    }
}

// ---------------------------------------------------------------------------
// Target-side precompute: per (b,f) row/col maxes of tmask + sum(tmask).
// ---------------------------------------------------------------------------
__global__ __launch_bounds__(96) void prep_kernel(const float* __restrict__ tmask)
{
    const int bf = blockIdx.x;
    const float* __restrict__ T = tmask + (size_t)bf * HWHW;
    const int i = threadIdx.x;      // 0..95
    float cmax = -1e30f, rmax = -1e30f, rs = 0.f;
    for (int h = 0; h < HW; h++) cmax = fmaxf(cmax, T[h*HW + i]);
    for (int w = 0; w < HW; w++) { float v = T[i*HW + w]; rmax = fmaxf(rmax, v); rs += v; }
    g_tcolmax[bf*HW + i] = cmax;
    g_trowmax[bf*HW + i] = rmax;

    __shared__ float sred[3];
    const int lane = i & 31, warp = i >> 5;
    #pragma unroll
    for (int off = 16; off; off >>= 1) rs += __shfl_xor_sync(0xffffffffu, rs, off);
    if (lane == 0) sred[warp] = rs;
    __syncthreads();
    if (i == 0) g_tsum[bf] = sred[0] + sred[1] + sred[2];
}

// ---------------------------------------------------------------------------
// Heavy kernel: one block (192 thr) per (b,f,q) 96x96 tile.
// Thread (c4 = tid%24, r0 = tid/24) owns float4 column c4 of rows r0+8k.
// Per element (branch-free):
//   xv = x*V;  zl = xv*S (S=±log2e);  e = exp2(zl) = e^z
//   sg = e/(1+e);  G = log2(1+e)*sg^2
//   f0 += G; f1 += S*G; A += sg; A2 += S*sg; maxes on xv
// Recover: focal = ln2*(0.5*f0 + 0.25*ln2*f1)
//          sum(sigmoid(x)) = tsum + ln2*A2
//          sum(sigmoid(x)*t) = tsum - 0.5*(A - ln2*A2)
// ---------------------------------------------------------------------------
__global__ __launch_bounds__(192) void mask_heavy(const float* __restrict__ masks)
{
    const int blk = blockIdx.x;          // ((b*NF+f)*NQ + q)
    const int bf  = blk / NQ;
    const int b   = bf / NF;
    const float4* __restrict__ X  = (const float4*)(masks + (size_t)blk * HWHW);
    const float4* __restrict__ Sp = (const float4*)(g_S   + (size_t)bf  * HWHW);
    const float4* __restrict__ Vp = (const float4*)(g_V   + (size_t)b   * HWHW);

    const int tid = threadIdx.x;
    const int c4  = tid % 24;   // float4 column
    const int r0  = tid / 24;   // 0..7 row tier

    __shared__ float rowpm[HW][24];   // per-row partial max (24 column chunks)
    __shared__ float cmS[8][HW];      // per-tier column maxes
    __shared__ float red[6][4];

    float f0 = 0.f, f1 = 0.f, A = 0.f, A2 = 0.f;
    float cm0 = -1e30f, cm1 = -1e30f, cm2 = -1e30f, cm3 = -1e30f;

    #pragma unroll 2
    for (int k = 0; k < 12; k++) {
        const int row = r0 + 8*k;
        const int off = row*24 + c4;             // float4 units
        const float4 x4 = __ldcs(X + off);       // streaming: don't thrash L1
        const float4 s4 = Sp[off];               // L1-resident
        const float4 v4 = Vp[off];               // L1-resident
        float rm = -1e30f;

        {   const float xv = x4.x * v4.x;  const float zl = xv * s4.x;
            const float e  = exp2f(zl);    const float ope = 1.f + e;
            const float u  = __fdividef(1.f, ope);
            const float sg = e * u;        const float lg = __log2f(ope);
            const float G  = lg * sg * sg;
            f0 += G;  f1 = fmaf(s4.x, G, f1);
            A  += sg; A2 = fmaf(s4.x, sg, A2);
            rm = fmaxf(rm, xv); cm0 = fmaxf(cm0, xv); }
        {   const float xv = x4.y * v4.y;  const float zl = xv * s4.y;
            const float e  = exp2f(zl);    const float ope = 1.f + e;
            const float u  = __fdividef(1.f, ope);
            const float sg = e * u;        const float lg = __log2f(ope);
            const float G  = lg * sg * sg;
            f0 += G;  f1 = fmaf(s4.y, G, f1);
            A  += sg; A2 = fmaf(s4.y, sg, A2);
            rm = fmaxf(rm, xv); cm1 = fmaxf(cm1, xv); }
        {   const float xv = x4.z * v4.z;  const float zl = xv * s4.z;
            const float e  = exp2f(zl);    const float ope = 1.f + e;
            const float u  = __fdividef(1.f, ope);
            const float sg = e * u;        const float lg = __log2f(ope);
            const float G  = lg * sg * sg;
            f0 += G;  f1 = fmaf(s4.z, G, f1);
            A  += sg; A2 = fmaf(s4.z, sg, A2);
            rm = fmaxf(rm, xv); cm2 = fmaxf(cm2, xv); }
        {   const float xv = x4.w * v4.w;  const float zl = xv * s4.w;
            const float e  = exp2f(zl);    const float ope = 1.f + e;
            const float u  = __fdividef(1.f, ope);
            const float sg = e * u;        const float lg = __log2f(ope);
            const float G  = lg * sg * sg;
            f0 += G;  f1 = fmaf(s4.w, G, f1);
            A  += sg; A2 = fmaf(s4.w, sg, A2);
            rm = fmaxf(rm, xv); cm3 = fmaxf(cm3, xv); }

        rowpm[row][c4] = rm;
    }

    // column partials (contiguous 16B -> one STS.128)
    *(float4*)&cmS[r0][4*c4] = make_float4(cm0, cm1, cm2, cm3);

    // accumulator reduce: intra-warp shfl, then smem across 6 warps
    const int lane = tid & 31, warp = tid >> 5;
    #pragma unroll
    for (int off = 16; off; off >>= 1) {
        f0 += __shfl_xor_sync(0xffffffffu, f0, off);
        f1 += __shfl_xor_sync(0xffffffffu, f1, off);
        A  += __shfl_xor_sync(0xffffffffu, A,  off);
        A2 += __shfl_xor_sync(0xffffffffu, A2, off);
    }
    if (lane == 0) { red[warp][0] = f0; red[warp][1] = f1; red[warp][2] = A; red[warp][3] = A2; }
    __syncthreads();

    if (tid == 0) {
        float F0 = 0.f, F1 = 0.f, At = 0.f, A2t = 0.f;
        #pragma unroll
        for (int i = 0; i < 6; i++) {
            F0 += red[i][0]; F1 += red[i][1]; At += red[i][2]; A2t += red[i][3];
        }
        const float ts = g_tsum[bf];
        g_focal[blk] = LN2 * (0.5f*F0 + 0.25f*LN2*F1);
        g_ssum [blk] = ts + LN2*A2t;
        g_stsum[blk] = ts - 0.5f*(At - LN2*A2t);
    }
    if (tid < HW) {
        // rowmax: reduce 24 chunk-maxes for row=tid (float4 LDS x6)
        const float4* rp = (const float4*)rowpm[tid];
        float4 a = rp[0];
        #pragma unroll
        for (int i = 1; i < 6; i++) {
            const float4 v = rp[i];
            a.x = fmaxf(a.x, v.x); a.y = fmaxf(a.y, v.y);
            a.z = fmaxf(a.z, v.z); a.w = fmaxf(a.w, v.w);
        }
        g_rowmax[(size_t)blk*HW + tid] = fmaxf(fmaxf(a.x, a.y), fmaxf(a.z, a.w));
    } else {
        // colmax: reduce 8 tier-maxes for col=tid-96
        const int col = tid - HW;
        float m = cmS[0][col];
        #pragma unroll
        for (int i = 1; i < 8; i++) m = fmaxf(m, cmS[i][col]);
        g_colmax[(size_t)blk*HW + col] = m;
    }
}

// ---------------------------------------------------------------------------
// Combine: per (b,q) block — proj dice over 768 maxes + class/bbox/giou + C.
// ---------------------------------------------------------------------------
__global__ __launch_bounds__(128) void combine_kernel(
    const float* __restrict__ logits, const float* __restrict__ boxes,
    const float* __restrict__ tboxes, const int* __restrict__ tvalid,
    float* __restrict__ out)
{
    const int bq = blockIdx.x;
    const int b  = bq / NQ;
    const int q  = bq % NQ;
    const int tid = threadIdx.x, lane = tid & 31, warp = tid >> 5;

    float v0 = 0.f, v1 = 0.f, v2 = 0.f, v3 = 0.f, v4 = 0.f, v5 = 0.f;
    for (int j = tid; j < NF*HW; j += 128) {
        const int f = j / HW, k = j % HW;
        const int src  = ((b*NF + f)*NQ + q)*HW + k;
        const int tsrc = (b*NF + f)*HW + k;
        const float ym = g_colmax[src];
        const float ty = g_tcolmax[tsrc];
        const float sy = __fdividef(1.f, 1.f + __expf(-ym));
        v0 += sy; v1 += (ty != 0.f) ? sy : 0.f; v2 += ty;
        const float xm = g_rowmax[src];
        const float tx = g_trowmax[tsrc];
        const float sx = __fdividef(1.f, 1.f + __expf(-xm));
        v3 += sx; v4 += (tx != 0.f) ? sx : 0.f; v5 += tx;
    }
    __shared__ float red[4][6];
    float v[6] = {v0, v1, v2, v3, v4, v5};
    #pragma unroll
    for (int off = 16; off; off >>= 1)
        #pragma unroll
        for (int m = 0; m < 6; m++) v[m] += __shfl_xor_sync(0xffffffffu, v[m], off);
    if (lane == 0)
        #pragma unroll
        for (int m = 0; m < 6; m++) red[warp][m] = v[m];
    __syncthreads();

    if (tid == 0) {
        float S[6];
        #pragma unroll
        for (int m = 0; m < 6; m++) S[m] = red[0][m] + red[1][m] + red[2][m] + red[3][m];

        float focal = 0.f, ss = 0.f, st = 0.f, ts = 0.f;
        #pragma unroll
        for (int f = 0; f < NF; f++) {
            const int idx = (b*NF + f)*NQ + q;
            focal += g_focal[idx]; ss += g_ssum[idx]; st += g_stsum[idx];
            ts += g_tsum[b*NF + f];
        }
        const float cost_mask = focal / D_TOT;
        const float cost_dice = -(2.f*st + 1.f) / (ss + ts + 1.f);
        const float dice_y = (2.f*S[1] + 1.f) / (S[0] + S[2] + 1.f);
        const float dice_x = (2.f*S[4] + 1.f) / (S[3] + S[5] + 1.f);
        const float cost_proj = -0.5f * (dice_y + dice_x);

        float cls = 0.f, wsum = 0.f, cb = 0.f, cg = 0.f;
        for (int f = 0; f < NF; f++) {
            const int bi = (b*NF + f)*NQ + q;
            const float lg = logits[bi];
            const float p  = __fdividef(1.f, 1.f + __expf(-lg));
            const float neg = 0.75f * p * p * (-__logf(1.f - p + 1e-8f));
            const float pos = 0.25f * (1.f - p) * (1.f - p) * (-__logf(p + 1e-8f));
            const float w = (tvalid[b*NF + f] != 0) ? 1.f : 0.f;
            cls += w * (pos - neg); wsum += w;

            const float* sb = boxes  + (size_t)bi * 4;
            const float* tb = tboxes + (size_t)(b*NF + f) * 4;
            cb += fabsf(sb[0]-tb[0]) + fabsf(sb[1]-tb[1])
                + fabsf(sb[2]-tb[2]) + fabsf(sb[3]-tb[3]);

            const float sx0 = sb[0] - 0.5f*sb[2], sy0 = sb[1] - 0.5f*sb[3];
            const float sx1 = sb[0] + 0.5f*sb[2], sy1 = sb[1] + 0.5f*sb[3];
            const float tx0 = tb[0] - 0.5f*tb[2], ty0 = tb[1] - 0.5f*tb[3];
            const float tx1 = tb[0] + 0.5f*tb[2], ty1 = tb[1] + 0.5f*tb[3];
            const float a1 = (sx1 - sx0) * (sy1 - sy0);
            const float a2 = (tx1 - tx0) * (ty1 - ty0);
            float iw = fminf(sx1, tx1) - fmaxf(sx0, tx0); iw = fmaxf(iw, 0.f);
            float ih = fminf(sy1, ty1) - fmaxf(sy0, ty0); ih = fmaxf(ih, 0.f);
            const float inter = iw * ih;
            const float uni = a1 + a2 - inter;
            const float iou = inter / uni;
            float cw = fmaxf(sx1, tx1) - fminf(sx0, tx0); cw = fmaxf(cw, 0.f);
            float ch = fmaxf(sy1, ty1) - fminf(sy0, ty0); ch = fmaxf(ch, 0.f);
            const float areac = cw * ch;
            const float giou = iou - (areac - uni) / areac;
            cg += -giou;
        }
        const float cost_class = cls / wsum;
        const float cost_bbox  = cb * (1.f / (float)NF);
        const float cost_giou  = cg * (1.f / (float)NF);

        out[bq] = cost_class + cost_bbox + cost_giou + cost_mask + cost_dice + cost_proj;
    }
}

// ---------------------------------------------------------------------------
// Argmin over q per batch (first-occurrence tie-break), write indices.
// ---------------------------------------------------------------------------
__global__ void argmin_kernel(float* __restrict__ out)
{
    const int b = threadIdx.x >> 5;
    const int lane = threadIdx.x & 31;
    if (b >= BS) return;
    float v[10];
    #pragma unroll
    for (int i = 0; i < 10; i++) {
        const int q = lane + 32*i;
        v[i] = (q < NQ) ? out[b*NQ + q] : 3.4e38f;
    }
    float best = 3.4e38f;
    int bi = NQ;
    #pragma unroll
    for (int i = 0; i < 10; i++) {
        if (v[i] < best) { best = v[i]; bi = lane + 32*i; }  // ascending i keeps earliest
    }
    #pragma unroll
    for (int off = 16; off; off >>= 1) {
        const float ov = __shfl_xor_sync(0xffffffffu, best, off);
        const int   oi = __shfl_xor_sync(0xffffffffu, bi,   off);
        if (ov < best || (ov == best && oi < bi)) { best = ov; bi = oi; }
    }
    if (lane == 0) {
        out[BS*NQ + b]      = (float)bi;  // src_ind
        out[BS*NQ + BS + b] = 0.f;        // tgt_ind
    }
}

extern "C" void kernel_launch(void* const* d_in, const int* in_sizes, int n_in,
                              void* d_out, int out_size)
{
    const float* logits = (const float*)d_in[0];  // (2,8,300,1)
    const float* boxes  = (const float*)d_in[1];  // (2,8,300,4)
    const float* masks  = (const float*)d_in[2];  // (2,8,300,96,96)
    const float* tmask  = (const float*)d_in[3];  // (2,8,96,96)
    const float* tboxes = (const float*)d_in[4];  // (2,8,4)
    const int*   tvalid = (const int*)d_in[5];    // (2,8)
    const unsigned char* vpad = (const unsigned char*)d_in[6];  // (2,96,96) bool
    float* out = (float*)d_out;                   // 600 C + 2 src + 2 tgt

    fill_sv<<<BS*NF, 256>>>(tmask, vpad);
    prep_kernel<<<BS*NF, 96>>>(tmask);
    mask_heavy<<<BS*NF*NQ, 192>>>(masks);
    combine_kernel<<<BS*NQ, 128>>>(logits, boxes, tboxes, tvalid, out);
    argmin_kernel<<<1, 64>>>(out);
}

// round 14
// speedup vs baseline: 1.6821x; 1.6821x over previous
#include <cuda_runtime.h>
#include <math.h>

#define NQ 300
#define NF 8
#define BS 2
#define HW 96
#define HWHW 9216
#define D_TOT 73728.0f   // NF*H*W
#define L2E 1.4426950408889634f
#define LN2 0.6931471805599453f

__device__ __forceinline__ float ex2_approx(float x) {
    float y; asm("ex2.approx.ftz.f32 %0, %1;" : "=f"(y) : "f"(x)); return y;
}

// Scratch (static __device__ — no allocation)
__device__ float g_focal [BS*NF*NQ];
__device__ float g_ssum  [BS*NF*NQ];
__device__ float g_stsum [BS*NF*NQ];
__device__ float g_colmax[BS*NF*NQ*HW];  // src_y pieces: max over h
__device__ float g_rowmax[BS*NF*NQ*HW];  // src_x pieces: max over w
__device__ float g_tcolmax[BS*NF*HW];
__device__ float g_trowmax[BS*NF*HW];
__device__ float g_tsum  [BS*NF];
__device__ float g_S[BS*NF*HWHW];        // per (bf,pixel): t ? -log2e : +log2e
__device__ float g_V[BS*HWHW];           // per (b,pixel): vpad ? 0 : 1

// ---------------------------------------------------------------------------
// Prep (merged): blocks 0..BS*NF-1: fill S + target row/col maxes + tsum.
//                blocks BS*NF..BS*NF+BS-1: fill V from vpad.
// ---------------------------------------------------------------------------
__global__ __launch_bounds__(256) void prep_all(
    const float* __restrict__ tmask, const unsigned char* __restrict__ vpad)
{
    if (blockIdx.x < BS*NF) {
        const int bf = blockIdx.x;
        const float* __restrict__ T = tmask + (size_t)bf * HWHW;
        for (int i = threadIdx.x; i < HWHW; i += 256)
            g_S[(size_t)bf*HWHW + i] = (T[i] != 0.f) ? -L2E : L2E;

        const int i = threadIdx.x;
        if (i < HW) {
            float cmax = -1e30f, rmax = -1e30f, rs = 0.f;
            for (int h = 0; h < HW; h++) cmax = fmaxf(cmax, T[h*HW + i]);
            for (int w = 0; w < HW; w++) { float v = T[i*HW + w]; rmax = fmaxf(rmax, v); rs += v; }
            g_tcolmax[bf*HW + i] = cmax;
            g_trowmax[bf*HW + i] = rmax;

            __shared__ float sred[3];
            const int lane = i & 31, warp = i >> 5;
            #pragma unroll
            for (int off = 16; off; off >>= 1) rs += __shfl_xor_sync(0xffffffffu, rs, off);
            if (lane == 0) sred[warp] = rs;
            __syncthreads();
            if (i == 0) g_tsum[bf] = sred[0] + sred[1] + sred[2];
        }
    } else {
        const int b = blockIdx.x - BS*NF;
        const unsigned char* __restrict__ VP = vpad + (size_t)b * HWHW;
        for (int i = threadIdx.x; i < HWHW; i += 256)
            g_V[(size_t)b*HWHW + i] = VP[i] ? 0.f : 1.f;
    }
}

// ---------------------------------------------------------------------------
// Heavy kernel: one block (192 thr) per (b,f,q) 96x96 tile.
// Per element (branch-free):
//   xv = x*V;  zl = xv*S (S=±log2e);  e = ex2.approx(zl) = e^z
//   sg = e/(1+e);  G = log2(1+e)*sg^2
// Recover: focal = ln2*(0.5*f0 + 0.25*ln2*f1)
//          sum(sigmoid(x)) = tsum + ln2*A2
//          sum(sigmoid(x)*t) = tsum - 0.5*(A - ln2*A2)
// ---------------------------------------------------------------------------
__global__ __launch_bounds__(192) void mask_heavy(const float* __restrict__ masks)
{
    const int blk = blockIdx.x;          // ((b*NF+f)*NQ + q)
    const int bf  = blk / NQ;
    const int b   = bf / NF;
    const float4* __restrict__ X  = (const float4*)(masks + (size_t)blk * HWHW);
    const float4* __restrict__ Sp = (const float4*)(g_S   + (size_t)bf  * HWHW);
    const float4* __restrict__ Vp = (const float4*)(g_V   + (size_t)b   * HWHW);

    const int tid = threadIdx.x;
    const int c4  = tid % 24;   // float4 column
    const int r0  = tid / 24;   // 0..7 row tier

    __shared__ float rowpm[HW][24];   // per-row partial max (24 column chunks)
    __shared__ float cmS[8][HW];      // per-tier column maxes
    __shared__ float red[6][4];

    float f0 = 0.f, f1 = 0.f, A = 0.f, A2 = 0.f;
    float cm0 = -1e30f, cm1 = -1e30f, cm2 = -1e30f, cm3 = -1e30f;

    #pragma unroll 2
    for (int k = 0; k < 12; k++) {
        const int row = r0 + 8*k;
        const int off = row*24 + c4;             // float4 units
        const float4 x4 = __ldcs(X + off);       // streaming: masks read once
        const float4 s4 = Sp[off];               // L1/L2-resident
        const float4 v4 = Vp[off];
        float rm = -1e30f;

        {   const float xv = x4.x * v4.x;  const float zl = xv * s4.x;
            const float e  = ex2_approx(zl); const float ope = 1.f + e;
            const float u  = __fdividef(1.f, ope);
            const float sg = e * u;        const float lg = __log2f(ope);
            const float G  = lg * sg * sg;
            f0 += G;  f1 = fmaf(s4.x, G, f1);
            A  += sg; A2 = fmaf(s4.x, sg, A2);
            rm = fmaxf(rm, xv); cm0 = fmaxf(cm0, xv); }
        {   const float xv = x4.y * v4.y;  const float zl = xv * s4.y;
            const float e  = ex2_approx(zl); const float ope = 1.f + e;
            const float u  = __fdividef(1.f, ope);
            const float sg = e * u;        const float lg = __log2f(ope);
            const float G  = lg * sg * sg;
            f0 += G;  f1 = fmaf(s4.y, G, f1);
            A  += sg; A2 = fmaf(s4.y, sg, A2);
            rm = fmaxf(rm, xv); cm1 = fmaxf(cm1, xv); }
        {   const float xv = x4.z * v4.z;  const float zl = xv * s4.z;
            const float e  = ex2_approx(zl); const float ope = 1.f + e;
            const float u  = __fdividef(1.f, ope);
            const float sg = e * u;        const float lg = __log2f(ope);
            const float G  = lg * sg * sg;
            f0 += G;  f1 = fmaf(s4.z, G, f1);
            A  += sg; A2 = fmaf(s4.z, sg, A2);
            rm = fmaxf(rm, xv); cm2 = fmaxf(cm2, xv); }
        {   const float xv = x4.w * v4.w;  const float zl = xv * s4.w;
            const float e  = ex2_approx(zl); const float ope = 1.f + e;
            const float u  = __fdividef(1.f, ope);
            const float sg = e * u;        const float lg = __log2f(ope);
            const float G  = lg * sg * sg;
            f0 += G;  f1 = fmaf(s4.w, G, f1);
            A  += sg; A2 = fmaf(s4.w, sg, A2);
            rm = fmaxf(rm, xv); cm3 = fmaxf(cm3, xv); }

        rowpm[row][c4] = rm;
    }

    // column partials (contiguous 16B -> one STS.128)
    *(float4*)&cmS[r0][4*c4] = make_float4(cm0, cm1, cm2, cm3);

    const int lane = tid & 31, warp = tid >> 5;
    #pragma unroll
    for (int off = 16; off; off >>= 1) {
        f0 += __shfl_xor_sync(0xffffffffu, f0, off);
        f1 += __shfl_xor_sync(0xffffffffu, f1, off);
        A  += __shfl_xor_sync(0xffffffffu, A,  off);
        A2 += __shfl_xor_sync(0xffffffffu, A2, off);
    }
    if (lane == 0) { red[warp][0] = f0; red[warp][1] = f1; red[warp][2] = A; red[warp][3] = A2; }
    __syncthreads();

    if (tid == 0) {
        float F0 = 0.f, F1 = 0.f, At = 0.f, A2t = 0.f;
        #pragma unroll
        for (int i = 0; i < 6; i++) {
            F0 += red[i][0]; F1 += red[i][1]; At += red[i][2]; A2t += red[i][3];
        }
        const float ts = g_tsum[bf];
        g_focal[blk] = LN2 * (0.5f*F0 + 0.25f*LN2*F1);
        g_ssum [blk] = ts + LN2*A2t;
        g_stsum[blk] = ts - 0.5f*(At - LN2*A2t);
    }
    if (tid < HW) {
        const float4* rp = (const float4*)rowpm[tid];
        float4 a = rp[0];
        #pragma unroll
        for (int i = 1; i < 6; i++) {
            const float4 v = rp[i];
            a.x = fmaxf(a.x, v.x); a.y = fmaxf(a.y, v.y);
            a.z = fmaxf(a.z, v.z); a.w = fmaxf(a.w, v.w);
        }
        g_rowmax[(size_t)blk*HW + tid] = fmaxf(fmaxf(a.x, a.y), fmaxf(a.z, a.w));
    } else {
        const int col = tid - HW;
        float m = cmS[0][col];
        #pragma unroll
        for (int i = 1; i < 8; i++) m = fmaxf(m, cmS[i][col]);
        g_colmax[(size_t)blk*HW + col] = m;
    }
}

// ---------------------------------------------------------------------------
// Combine: one WARP per (b,q). 8 warps/block, grid = 600/8.
// Proj dice over 768 maxes across 32 lanes; frame tail across 8 lanes.
// ---------------------------------------------------------------------------
__global__ __launch_bounds__(256) void combine_kernel(
    const float* __restrict__ logits, const float* __restrict__ boxes,
    const float* __restrict__ tboxes, const int* __restrict__ tvalid,
    float* __restrict__ out)
{
    const int bq = blockIdx.x * 8 + (threadIdx.x >> 5);
    if (bq >= BS*NQ) return;
    const int b  = bq / NQ;
    const int q  = bq % NQ;
    const int lane = threadIdx.x & 31;

    // ---- projection sums over NF*HW = 768 elements ----
    float v0 = 0.f, v1 = 0.f, v2 = 0.f, v3 = 0.f, v4 = 0.f, v5 = 0.f;
    #pragma unroll
    for (int j = lane; j < NF*HW; j += 32) {
        const int f = j / HW, k = j % HW;
        const int src  = ((b*NF + f)*NQ + q)*HW + k;
        const int tsrc = (b*NF + f)*HW + k;
        const float ym = g_colmax[src];
        const float ty = g_tcolmax[tsrc];
        const float sy = __fdividef(1.f, 1.f + ex2_approx(-L2E*ym));
        v0 += sy; v1 += (ty != 0.f) ? sy : 0.f; v2 += ty;
        const float xm = g_rowmax[src];
        const float tx = g_trowmax[tsrc];
        const float sx = __fdividef(1.f, 1.f + ex2_approx(-L2E*xm));
        v3 += sx; v4 += (tx != 0.f) ? sx : 0.f; v5 += tx;
    }

    // ---- per-frame terms, lanes 0..7 own f = lane ----
    float cls = 0.f, wv = 0.f, cb = 0.f, cg = 0.f;
    float focal = 0.f, ss = 0.f, st = 0.f, ts = 0.f;
    if (lane < NF) {
        const int f  = lane;
        const int idx = (b*NF + f)*NQ + q;
        focal = g_focal[idx]; ss = g_ssum[idx]; st = g_stsum[idx];
        ts = g_tsum[b*NF + f];

        const float lg = logits[idx];
        const float p  = __fdividef(1.f, 1.f + __expf(-lg));
        const float neg = 0.75f * p * p * (-__logf(1.f - p + 1e-8f));
        const float pos = 0.25f * (1.f - p) * (1.f - p) * (-__logf(p + 1e-8f));
        wv = (tvalid[b*NF + f] != 0) ? 1.f : 0.f;
        cls = wv * (pos - neg);

        const float* sb = boxes  + (size_t)idx * 4;
        const float* tb = tboxes + (size_t)(b*NF + f) * 4;
        cb = fabsf(sb[0]-tb[0]) + fabsf(sb[1]-tb[1])
           + fabsf(sb[2]-tb[2]) + fabsf(sb[3]-tb[3]);

        const float sx0 = sb[0] - 0.5f*sb[2], sy0 = sb[1] - 0.5f*sb[3];
        const float sx1 = sb[0] + 0.5f*sb[2], sy1 = sb[1] + 0.5f*sb[3];
        const float tx0 = tb[0] - 0.5f*tb[2], ty0 = tb[1] - 0.5f*tb[3];
        const float tx1 = tb[0] + 0.5f*tb[2], ty1 = tb[1] + 0.5f*tb[3];
        const float a1 = (sx1 - sx0) * (sy1 - sy0);
        const float a2 = (tx1 - tx0) * (ty1 - ty0);
        float iw = fminf(sx1, tx1) - fmaxf(sx0, tx0); iw = fmaxf(iw, 0.f);
        float ih = fminf(sy1, ty1) - fmaxf(sy0, ty0); ih = fmaxf(ih, 0.f);
        const float inter = iw * ih;
        const float uni = a1 + a2 - inter;
        const float iou = inter / uni;
        float cw = fmaxf(sx1, tx1) - fminf(sx0, tx0); cw = fmaxf(cw, 0.f);
        float ch = fmaxf(sy1, ty1) - fminf(sy0, ty0); ch = fmaxf(ch, 0.f);
        const float areac = cw * ch;
        cg = -(iou - (areac - uni) / areac);
    }

    // ---- warp reductions (proj over 32 lanes; frame terms live in lanes<8,
    //      zeros elsewhere, so a full 32-lane sum is correct for both) ----
    #pragma unroll
    for (int off = 16; off; off >>= 1) {
        v0 += __shfl_xor_sync(0xffffffffu, v0, off);
        v1 += __shfl_xor_sync(0xffffffffu, v1, off);
        v2 += __shfl_xor_sync(0xffffffffu, v2, off);
        v3 += __shfl_xor_sync(0xffffffffu, v3, off);
        v4 += __shfl_xor_sync(0xffffffffu, v4, off);
        v5 += __shfl_xor_sync(0xffffffffu, v5, off);
        cls += __shfl_xor_sync(0xffffffffu, cls, off);
        wv  += __shfl_xor_sync(0xffffffffu, wv,  off);
        cb  += __shfl_xor_sync(0xffffffffu, cb,  off);
        cg  += __shfl_xor_sync(0xffffffffu, cg,  off);
        focal += __shfl_xor_sync(0xffffffffu, focal, off);
        ss  += __shfl_xor_sync(0xffffffffu, ss,  off);
        st  += __shfl_xor_sync(0xffffffffu, st,  off);
        ts  += __shfl_xor_sync(0xffffffffu, ts,  off);
    }

    if (lane == 0) {
        const float cost_mask = focal / D_TOT;
        const float cost_dice = -(2.f*st + 1.f) / (ss + ts + 1.f);
        const float dice_y = (2.f*v1 + 1.f) / (v0 + v2 + 1.f);
        const float dice_x = (2.f*v4 + 1.f) / (v3 + v5 + 1.f);
        const float cost_proj = -0.5f * (dice_y + dice_x);
        const float cost_class = cls / wv;
        const float cost_bbox  = cb * (1.f / (float)NF);
        const float cost_giou  = cg * (1.f / (float)NF);
        out[bq] = cost_class + cost_bbox + cost_giou + cost_mask + cost_dice + cost_proj;
    }
}

// ---------------------------------------------------------------------------
// Argmin over q per batch (first-occurrence tie-break), write indices.
// ---------------------------------------------------------------------------
__global__ void argmin_kernel(float* __restrict__ out)
{
    const int b = threadIdx.x >> 5;
    const int lane = threadIdx.x & 31;
    if (b >= BS) return;
    float v[10];
    #pragma unroll
    for (int i = 0; i < 10; i++) {
        const int q = lane + 32*i;
        v[i] = (q < NQ) ? out[b*NQ + q] : 3.4e38f;
    }
    float best = 3.4e38f;
    int bi = NQ;
    #pragma unroll
    for (int i = 0; i < 10; i++) {
        if (v[i] < best) { best = v[i]; bi = lane + 32*i; }  // ascending i keeps earliest
    }
    #pragma unroll
    for (int off = 16; off; off >>= 1) {
        const float ov = __shfl_xor_sync(0xffffffffu, best, off);
        const int   oi = __shfl_xor_sync(0xffffffffu, bi,   off);
        if (ov < best || (ov == best && oi < bi)) { best = ov; bi = oi; }
    }
    if (lane == 0) {
        out[BS*NQ + b]      = (float)bi;  // src_ind
        out[BS*NQ + BS + b] = 0.f;        // tgt_ind
    }
}

extern "C" void kernel_launch(void* const* d_in, const int* in_sizes, int n_in,
                              void* d_out, int out_size)
{
    const float* logits = (const float*)d_in[0];  // (2,8,300,1)
    const float* boxes  = (const float*)d_in[1];  // (2,8,300,4)
    const float* masks  = (const float*)d_in[2];  // (2,8,300,96,96)
    const float* tmask  = (const float*)d_in[3];  // (2,8,96,96)
    const float* tboxes = (const float*)d_in[4];  // (2,8,4)
    const int*   tvalid = (const int*)d_in[5];    // (2,8)
    const unsigned char* vpad = (const unsigned char*)d_in[6];  // (2,96,96) bool
    float* out = (float*)d_out;                   // 600 C + 2 src + 2 tgt

    prep_all<<<BS*NF + BS, 256>>>(tmask, vpad);
    mask_heavy<<<BS*NF*NQ, 192>>>(masks);
    combine_kernel<<<(BS*NQ + 7)/8, 256>>>(logits, boxes, tboxes, tvalid, out);
    argmin_kernel<<<1, 64>>>(out);
}